// round 5
// baseline (speedup 1.0000x reference)
#include <cuda_runtime.h>

#define B_ 512
#define S_ 512
#define T_ 128
#define NCTA 256
// START_ID = 0, END_ID = 1

__device__ float g_partial[B_];

__device__ __forceinline__ unsigned long long ffma2(unsigned long long a,
                                                    unsigned long long b,
                                                    unsigned long long c) {
    unsigned long long d;
    asm("fma.rn.f32x2 %0, %1, %2, %3;" : "=l"(d) : "l"(a), "l"(b), "l"(c));
    return d;
}

__device__ __forceinline__ float frcp(float a) {
    float r;
    asm("rcp.approx.f32 %0, %1;" : "=f"(r) : "f"(a));
    return r;
}

// S_i = sum_j E_ij * p_j  (E in regs as f32x2 pairs, p broadcast from smem)
__device__ __forceinline__ float matvec128(const unsigned long long* E2, const float* p)
{
    unsigned long long c0 = 0ull, c1 = 0ull, c2 = 0ull, c3 = 0ull;
    const longlong2* p4 = reinterpret_cast<const longlong2*>(p);
    #pragma unroll
    for (int j = 0; j < 16; j++) {
        longlong2 pa = p4[2 * j];
        longlong2 pb = p4[2 * j + 1];
        c0 = ffma2(E2[4 * j + 0], (unsigned long long)pa.x, c0);
        c1 = ffma2(E2[4 * j + 1], (unsigned long long)pa.y, c1);
        c2 = ffma2(E2[4 * j + 2], (unsigned long long)pb.x, c2);
        c3 = ffma2(E2[4 * j + 3], (unsigned long long)pb.y, c3);
    }
    float2 f0 = *reinterpret_cast<float2*>(&c0);
    float2 f1 = *reinterpret_cast<float2*>(&c1);
    float2 f2 = *reinterpret_cast<float2*>(&c2);
    float2 f3 = *reinterpret_cast<float2*>(&c3);
    return ((f0.x + f0.y) + (f1.x + f1.y)) + ((f2.x + f2.y) + (f3.x + f3.y));
}

__global__ void __launch_bounds__(128, 2)
crf_dual_kernel(const float* __restrict__ x, const int* __restrict__ tags,
                const float* __restrict__ mask, const float* __restrict__ tr)
{
    const int bA   = blockIdx.x;
    const int bB   = blockIdx.x + NCTA;
    const int tid  = threadIdx.x;
    const int lane = tid & 31;
    const int wid  = tid >> 5;

    __shared__ __align__(16) float p_sh[2][2][T_];   // [chain][buf][tag]
    __shared__ float d_sh[2][2];
    __shared__ float rb[8];
    __shared__ int   tags_shA[S_];
    __shared__ int   tags_shB[S_];

    const float* xbA = x + (size_t)bA * (S_ * T_);
    const float* xbB = x + (size_t)bB * (S_ * T_);

    // ---- stage tags (coalesced) ----
    #pragma unroll
    for (int k = 0; k < 4; k++) {
        tags_shA[tid + k * 128] = tags[bA * S_ + tid + k * 128];
        tags_shB[tid + k * 128] = tags[bB * S_ + tid + k * 128];
    }

    // ---- lengths ----
    const float* mA = mask + bA * S_;
    const float* mB = mask + bB * S_;
    float msA = mA[tid] + mA[tid + 128] + mA[tid + 256] + mA[tid + 384];
    float msB = mB[tid] + mB[tid + 128] + mB[tid + 256] + mB[tid + 384];
    #pragma unroll
    for (int o = 16; o; o >>= 1) {
        msA += __shfl_xor_sync(0xffffffffu, msA, o);
        msB += __shfl_xor_sync(0xffffffffu, msB, o);
    }
    if (lane == 0) { rb[wid] = msA; rb[4 + wid] = msB; }
    __syncthreads();
    const int lenA = (int)(rb[0] + rb[1] + rb[2] + rb[3] + 0.5f);
    const int lenB = (int)(rb[4] + rb[5] + rb[6] + rb[7] + 0.5f);
    __syncthreads();

    // ---- gold score partials ----
    float goldA = 0.f, goldB = 0.f;
    for (int t = tid; t < lenA; t += 128) {
        int t1 = tags_shA[t + 1], t0 = tags_shA[t];
        goldA += xbA[t * T_ + t1] + tr[t1 * T_ + t0];
    }
    for (int t = tid; t < lenB; t += 128) {
        int t1 = tags_shB[t + 1], t0 = tags_shB[t];
        goldB += xbB[t * T_ + t1] + tr[t1 * T_ + t0];
    }

    // ---- E = exp(Tr): thread i holds row i packed as f32x2 ----
    unsigned long long E2[64];
    const float4* trow4 = reinterpret_cast<const float4*>(tr + tid * T_);
    #pragma unroll
    for (int k = 0; k < 32; k++) {
        float4 t4 = trow4[k];
        float2 ea, eb;
        ea.x = __expf(t4.x); ea.y = __expf(t4.y);
        eb.x = __expf(t4.z); eb.y = __expf(t4.w);
        E2[2 * k]     = *reinterpret_cast<unsigned long long*>(&ea);
        E2[2 * k + 1] = *reinterpret_cast<unsigned long long*>(&eb);
    }
    const float ET = __expf(tr[1 * T_ + tid]);   // exp(Tr[END, i])

    // ---- linear-domain state ----
    // q_i = exp(alpha_i)/C ; C grows by lagged S0 each step; L = log C.
    float qA = (tid == 0) ? 1.f : 0.f;           // exp(alpha0): [1,0,...,0]
    float qB = qA;
    float s0A = 1.f, s0B = 1.f;                  // S_{t-1}[0] (tid 0's value used)
    float LA = 0.f, LB = 0.f;
    float exA = __expf(xbA[tid]);                // exp(x_0)
    float exB = __expf(xbB[tid]);

    const int lenMin = lenA < lenB ? lenA : lenB;
    int buf = 0;

    // ---- main loop: both chains active, branch-free ----
    for (int t = 0; t < lenMin; t++) {
        p_sh[0][buf][tid] = qA;
        p_sh[1][buf][tid] = qB;
        if (tid == 0) { d_sh[0][buf] = s0A; d_sh[1][buf] = s0B; }
        __syncthreads();

        float a0A = d_sh[0][buf];
        float a0B = d_sh[1][buf];
        float wA = exA * frcp(a0A);              // off critical path
        float wB = exB * frcp(a0B);

        float sA = matvec128(E2, p_sh[0][buf]);
        float sB = matvec128(E2, p_sh[1][buf]);

        float xnA = xbA[(t + 1) * T_ + tid];     // t+1 <= lenMin <= 510 < S_
        float xnB = xbB[(t + 1) * T_ + tid];

        qA = wA * sA;  s0A = sA;  LA += __logf(a0A);
        qB = wB * sB;  s0B = sB;  LB += __logf(a0B);
        exA = __expf(xnA);
        exB = __expf(xnB);
        buf ^= 1;
    }

    // ---- tail: only the longer chain ----
    if (lenA > lenMin) {
        for (int t = lenMin; t < lenA; t++) {
            p_sh[0][buf][tid] = qA;
            if (tid == 0) d_sh[0][buf] = s0A;
            __syncthreads();
            float a0 = d_sh[0][buf];
            float w  = exA * frcp(a0);
            float s  = matvec128(E2, p_sh[0][buf]);
            float xn = xbA[(t + 1) * T_ + tid];
            qA = w * s;  s0A = s;  LA += __logf(a0);
            exA = __expf(xn);
            buf ^= 1;
        }
    } else if (lenB > lenMin) {
        for (int t = lenMin; t < lenB; t++) {
            p_sh[1][buf][tid] = qB;
            if (tid == 0) d_sh[1][buf] = s0B;
            __syncthreads();
            float a0 = d_sh[1][buf];
            float w  = exB * frcp(a0);
            float s  = matvec128(E2, p_sh[1][buf]);
            float xn = xbB[(t + 1) * T_ + tid];
            qB = w * s;  s0B = s;  LB += __logf(a0);
            exB = __expf(xn);
            buf ^= 1;
        }
    }

    // ---- fwd = L + log( sum_i q_i * exp(Tr[END,i]) ) ----
    float vA = qA * ET;
    float vB = qB * ET;
    #pragma unroll
    for (int o = 16; o; o >>= 1) {
        vA += __shfl_xor_sync(0xffffffffu, vA, o);
        vB += __shfl_xor_sync(0xffffffffu, vB, o);
    }
    __syncthreads();
    if (lane == 0) { rb[wid] = vA; rb[4 + wid] = vB; }
    __syncthreads();
    float sumA = rb[0] + rb[1] + rb[2] + rb[3];
    float sumB = rb[4] + rb[5] + rb[6] + rb[7];
    float fwdA = LA + __logf(sumA);
    float fwdB = LB + __logf(sumB);

    // ---- gold reduce ----
    #pragma unroll
    for (int o = 16; o; o >>= 1) {
        goldA += __shfl_xor_sync(0xffffffffu, goldA, o);
        goldB += __shfl_xor_sync(0xffffffffu, goldB, o);
    }
    __syncthreads();
    if (lane == 0) { rb[wid] = goldA; rb[4 + wid] = goldB; }
    __syncthreads();
    if (tid == 0) {
        float gA = rb[0] + rb[1] + rb[2] + rb[3] + tr[1 * T_ + tags_shA[lenA]];
        float gB = rb[4] + rb[5] + rb[6] + rb[7] + tr[1 * T_ + tags_shB[lenB]];
        g_partial[bA] = fwdA - gA;
        g_partial[bB] = fwdB - gB;
    }
}

__global__ void crf_finalize_kernel(float* __restrict__ out)
{
    int tid = threadIdx.x;  // 512 threads
    float v = g_partial[tid];
    #pragma unroll
    for (int o = 16; o; o >>= 1) v += __shfl_xor_sync(0xffffffffu, v, o);
    __shared__ float rb[16];
    if ((tid & 31) == 0) rb[tid >> 5] = v;
    __syncthreads();
    if (tid < 32) {
        float s = (tid < 16) ? rb[tid] : 0.f;
        #pragma unroll
        for (int o = 8; o; o >>= 1) s += __shfl_xor_sync(0xffffffffu, s, o);
        if (tid == 0) out[0] = s * (1.0f / 512.0f);
    }
}

extern "C" void kernel_launch(void* const* d_in, const int* in_sizes, int n_in,
                              void* d_out, int out_size)
{
    const float* x    = (const float*)d_in[0];
    const int*   tags = (const int*)d_in[1];
    const float* mask = (const float*)d_in[2];
    const float* tr   = (const float*)d_in[3];
    (void)in_sizes; (void)n_in; (void)out_size;

    crf_dual_kernel<<<NCTA, 128>>>(x, tags, mask, tr);
    crf_finalize_kernel<<<1, 512>>>((float*)d_out);
}